// round 2
// baseline (speedup 1.0000x reference)
#include <cuda_runtime.h>

#define B 512
#define D 128
#define TI 4

// ---------------- device scratch (no allocation allowed) ----------------
__device__ float g_e1n[3][B][D];     // normalized emb1, row-major [l][i][d]
__device__ float g_e2nT[3][D][B];    // normalized emb2, TRANSPOSED [l][d][j]
__device__ float g_c1p[2][B][D];     // cert1_{1,2} * 0.5*alpha_{1,2}
__device__ float g_c2T[2][D][B];     // cert2_{1,2} transposed [l][d][j]
__device__ float g_bp[2][D];         // 0.5*beta_{1,2}
__device__ int   g_widx[2][D][3];    // top-3 row indices per column
__device__ float g_wval[2][D][3];    // column-normalized top-3 weights

__device__ __forceinline__ float tanh_approx(float x) {
    float y;
    asm("tanh.approx.f32 %0, %1;" : "=f"(y) : "f"(x));
    return y;
}

// ---------------- prep: normalize / transpose / scale ----------------
__global__ void prep_kernel(
    const float* __restrict__ e1_0, const float* __restrict__ e1_1, const float* __restrict__ e1_2,
    const float* __restrict__ e2_0, const float* __restrict__ e2_1, const float* __restrict__ e2_2,
    const float* __restrict__ c1_1, const float* __restrict__ c1_2,
    const float* __restrict__ c2_1, const float* __restrict__ c2_2,
    const float* __restrict__ a_1,  const float* __restrict__ a_2,
    const float* __restrict__ b_1,  const float* __restrict__ b_2)
{
    __shared__ float sp[4];
    int bid = blockIdx.x;
    int d = threadIdx.x;   // 0..127

    if (bid < 3072) {
        // L2-normalize one embedding row
        int which = bid / 1536;            // 0 = emb1, 1 = emb2
        int t = bid % 1536;
        int l = t / B, r = t % B;
        const float* src = (which == 0)
            ? (l == 0 ? e1_0 : (l == 1 ? e1_1 : e1_2))
            : (l == 0 ? e2_0 : (l == 1 ? e2_1 : e2_2));
        float x = src[r * D + d];
        float ss = x * x;
        #pragma unroll
        for (int o = 16; o; o >>= 1) ss += __shfl_xor_sync(0xffffffffu, ss, o);
        if ((d & 31) == 0) sp[d >> 5] = ss;
        __syncthreads();
        float tot = sp[0] + sp[1] + sp[2] + sp[3];
        float inv = 1.0f / fmaxf(sqrtf(tot), 1e-12f);
        float v = x * inv;
        if (which == 0) g_e1n[l][r][d]  = v;
        else            g_e2nT[l][d][r] = v;
    } else if (bid < 4096) {
        // c1p = cert1 * 0.5*alpha
        int t = bid - 3072;
        int l = t / B, r = t % B;
        const float* c = (l == 0) ? c1_1 : c1_2;
        const float* a = (l == 0) ? a_1  : a_2;
        g_c1p[l][r][d] = c[r * D + d] * (0.5f * a[d]);
    } else if (bid < 5120) {
        // cert2 transpose
        int t = bid - 4096;
        int l = t / B, r = t % B;
        const float* c = (l == 0) ? c2_1 : c2_2;
        g_c2T[l][d][r] = c[r * D + d];
    } else {
        g_bp[0][d] = 0.5f * b_1[d];
        g_bp[1][d] = 0.5f * b_2[d];
    }
}

// ---------------- top-3 per column + column normalization ----------------
__global__ void topk_kernel(const float* __restrict__ link0,
                            const float* __restrict__ link1)
{
    int t = threadIdx.x;            // 0..255
    int m = t >> 7, e = t & 127;
    const float* L = m ? link1 : link0;
    float v0 = -1e30f, v1 = -1e30f, v2 = -1e30f;
    int   i0 = 0, i1 = 0, i2 = 0;
    for (int d = 0; d < D; ++d) {
        float w = L[d * D + e];     // column e, row d
        if (w > v0)      { v2 = v1; i2 = i1; v1 = v0; i1 = i0; v0 = w; i0 = d; }
        else if (w > v1) { v2 = v1; i2 = i1; v1 = w;  i1 = d; }
        else if (w > v2) { v2 = w;  i2 = d; }
    }
    float inv = 1.0f / (v0 + v1 + v2 + 1e-8f);
    g_widx[m][e][0] = i0; g_widx[m][e][1] = i1; g_widx[m][e][2] = i2;
    g_wval[m][e][0] = v0 * inv; g_wval[m][e][1] = v1 * inv; g_wval[m][e][2] = v2 * inv;
}

// ---------------- fused similarity kernel ----------------
// block = (32 j-lanes, 8 e-groups); each thread owns 16 channels of one pair.
// nh[d][j] rows are 32 floats -> every shared access is broadcast or
// row-consecutive: zero bank conflicts. All LDGs coalesced via transposed j-side.
__global__ __launch_bounds__(256) void avsl_main_kernel(float* __restrict__ out)
{
    __shared__ float nh[D][32];        // 16 KB: nh[d][j] for the current i
    __shared__ float sI[5 * D];        // e1n l0,l1,l2 ; c1p l1,l2 (current i)
    __shared__ float sBP[2][D];
    __shared__ int   sWidx[2][D][3];
    __shared__ float sWval[2][D][3];
    __shared__ float sRed[8][32];

    const int j   = threadIdx.x;       // 0..31
    const int g   = threadIdx.y;       // 0..7
    const int tid = g * 32 + j;
    const int j0  = blockIdx.x * 32;
    const int i0  = blockIdx.y * TI;
    const int jj  = j0 + j;

    // stage W + beta' once per block
    for (int t = tid; t < 2 * D * 3; t += 256) {
        ((int*)sWidx)[t]   = ((const int*)g_widx)[t];
        ((float*)sWval)[t] = ((const float*)g_wval)[t];
    }
    for (int t = tid; t < 2 * D; t += 256)
        ((float*)sBP)[t] = ((const float*)g_bp)[t];

    for (int ii = 0; ii < TI; ++ii) {
        const int i = i0 + ii;
        __syncthreads();   // protect sI/sRed/nh reuse from previous iteration
        for (int t = tid; t < 5 * D; t += 256) {
            int seg = t >> 7, d = t & 127;
            sI[t] = (seg < 3) ? g_e1n[seg][i][d] : g_c1p[seg - 3][i][d];
        }
        __syncthreads();

        // ---- layer 0 ----
        #pragma unroll
        for (int k = 0; k < 16; ++k) {
            int e = g * 16 + k;
            float v = sI[e] - g_e2nT[0][e][jj];
            nh[e][j] = v * v;
        }
        __syncthreads();

        // ---- layer 1 ----
        float tnh[16];
        #pragma unroll
        for (int k = 0; k < 16; ++k) {
            int e = g * 16 + k;
            float s = sWval[0][e][0] * nh[sWidx[0][e][0]][j];
            s = fmaf(sWval[0][e][1], nh[sWidx[0][e][1]][j], s);
            s = fmaf(sWval[0][e][2], nh[sWidx[0][e][2]][j], s);
            float v  = sI[D + e] - g_e2nT[1][e][jj];
            float n1 = v * v;
            float arg = fmaf(sI[3 * D + e], g_c2T[0][e][jj], sBP[0][e]);
            float P   = fmaf(0.5f, tanh_approx(arg), 0.5f);
            tnh[k] = fmaf(P, n1 - s, s);
        }
        __syncthreads();   // all layer-1 gathers done before nh overwrite
        #pragma unroll
        for (int k = 0; k < 16; ++k) nh[g * 16 + k][j] = tnh[k];
        __syncthreads();

        // ---- layer 2 + channel sum ----
        float acc = 0.0f;
        #pragma unroll
        for (int k = 0; k < 16; ++k) {
            int e = g * 16 + k;
            float s = sWval[1][e][0] * nh[sWidx[1][e][0]][j];
            s = fmaf(sWval[1][e][1], nh[sWidx[1][e][1]][j], s);
            s = fmaf(sWval[1][e][2], nh[sWidx[1][e][2]][j], s);
            float v  = sI[2 * D + e] - g_e2nT[2][e][jj];
            float n2 = v * v;
            float arg = fmaf(sI[4 * D + e], g_c2T[1][e][jj], sBP[1][e]);
            float P   = fmaf(0.5f, tanh_approx(arg), 0.5f);
            acc += fmaf(P, n2 - s, s);
        }
        sRed[g][j] = acc;
        __syncthreads();
        if (g == 0) {
            float tot = sRed[0][j] + sRed[1][j] + sRed[2][j] + sRed[3][j]
                      + sRed[4][j] + sRed[5][j] + sRed[6][j] + sRed[7][j];
            out[i * B + jj] = tot;
        }
    }
}

// ---------------- launch ----------------
extern "C" void kernel_launch(void* const* d_in, const int* in_sizes, int n_in,
                              void* d_out, int out_size)
{
    (void)n_in; (void)out_size;

    const float *e1_0, *e1_1, *e1_2, *e2_0, *e2_1, *e2_2;
    const float *c1_1, *c1_2, *c2_1, *c2_2;
    const float *a_1, *a_2, *b_1, *b_2;
    const float *link0, *link1;

    // Detect input ordering at runtime via element counts.
    // setup_inputs() dict order: per-layer interleaved
    //   [emb1_l, emb2_l, cert1_l, cert2_l, alpha_l, beta_l] x3, link_0, link_1
    //   -> in_sizes[4] == 128 (alpha_0)
    // reference() signature order: grouped
    //   emb1_0..2, emb2_0..2, cert1_0..2, cert2_0..2, alpha_0..2, beta_0..2, links
    //   -> in_sizes[4] == 65536 (emb2_1)
    if (in_sizes[4] == 128) {
        // dict insertion order (interleaved per layer)
        e1_0 = (const float*)d_in[0];   e2_0 = (const float*)d_in[1];
        e1_1 = (const float*)d_in[6];   e2_1 = (const float*)d_in[7];
        e1_2 = (const float*)d_in[12];  e2_2 = (const float*)d_in[13];
        c1_1 = (const float*)d_in[8];   c2_1 = (const float*)d_in[9];
        c1_2 = (const float*)d_in[14];  c2_2 = (const float*)d_in[15];
        a_1  = (const float*)d_in[10];  b_1  = (const float*)d_in[11];
        a_2  = (const float*)d_in[16];  b_2  = (const float*)d_in[17];
        link0 = (const float*)d_in[18]; link1 = (const float*)d_in[19];
    } else {
        // function-signature order (grouped)
        e1_0 = (const float*)d_in[0];   e1_1 = (const float*)d_in[1];
        e1_2 = (const float*)d_in[2];
        e2_0 = (const float*)d_in[3];   e2_1 = (const float*)d_in[4];
        e2_2 = (const float*)d_in[5];
        c1_1 = (const float*)d_in[7];   c1_2 = (const float*)d_in[8];
        c2_1 = (const float*)d_in[10];  c2_2 = (const float*)d_in[11];
        a_1  = (const float*)d_in[13];  a_2  = (const float*)d_in[14];
        b_1  = (const float*)d_in[16];  b_2  = (const float*)d_in[17];
        link0 = (const float*)d_in[18]; link1 = (const float*)d_in[19];
    }

    prep_kernel<<<5121, 128>>>(e1_0, e1_1, e1_2, e2_0, e2_1, e2_2,
                               c1_1, c1_2, c2_1, c2_2, a_1, a_2, b_1, b_2);
    topk_kernel<<<1, 256>>>(link0, link1);

    dim3 grid(B / 32, B / TI);   // (16, 128)
    dim3 blk(32, 8);
    avsl_main_kernel<<<grid, blk>>>((float*)d_out);
}

// round 3
// speedup vs baseline: 1.3759x; 1.3759x over previous
#include <cuda_runtime.h>

#define B 512
#define D 128
#define TI 2
#define JT 64            // j-tile per block
#define NHSTRIDE 64

// ---------------- device scratch (no allocation allowed) ----------------
__device__ float g_e1n[3][B][D];     // normalized emb1, row-major [l][i][d]
__device__ float g_e2nT[3][D][B];    // normalized emb2, TRANSPOSED [l][d][j]
__device__ float g_c1p[2][B][D];     // cert1_{1,2} * 0.5*alpha_{1,2}
__device__ float g_c2T[2][D][B];     // cert2_{1,2} transposed [l][d][j]
__device__ float g_bp[2][D];         // 0.5*beta_{1,2}
__device__ int4   g_widx4[2][D];     // top-3 row indices * NHSTRIDE (premul), .w unused
__device__ float4 g_wval4[2][D];     // column-normalized top-3 weights, .w unused

__device__ __forceinline__ float tanh_approx(float x) {
    float y;
    asm("tanh.approx.f32 %0, %1;" : "=f"(y) : "f"(x));
    return y;
}

// ---------------- prep: normalize / transpose / scale / topk ----------------
__global__ void prep_kernel(
    const float* __restrict__ e1_0, const float* __restrict__ e1_1, const float* __restrict__ e1_2,
    const float* __restrict__ e2_0, const float* __restrict__ e2_1, const float* __restrict__ e2_2,
    const float* __restrict__ c1_1, const float* __restrict__ c1_2,
    const float* __restrict__ c2_1, const float* __restrict__ c2_2,
    const float* __restrict__ a_1,  const float* __restrict__ a_2,
    const float* __restrict__ b_1,  const float* __restrict__ b_2,
    const float* __restrict__ link0, const float* __restrict__ link1)
{
    __shared__ float sp[4];
    int bid = blockIdx.x;
    int d = threadIdx.x;   // 0..127

    if (bid < 3072) {
        // L2-normalize one embedding row
        int which = bid / 1536;            // 0 = emb1, 1 = emb2
        int t = bid % 1536;
        int l = t / B, r = t % B;
        const float* src = (which == 0)
            ? (l == 0 ? e1_0 : (l == 1 ? e1_1 : e1_2))
            : (l == 0 ? e2_0 : (l == 1 ? e2_1 : e2_2));
        float x = src[r * D + d];
        float ss = x * x;
        #pragma unroll
        for (int o = 16; o; o >>= 1) ss += __shfl_xor_sync(0xffffffffu, ss, o);
        if ((d & 31) == 0) sp[d >> 5] = ss;
        __syncthreads();
        float tot = sp[0] + sp[1] + sp[2] + sp[3];
        float inv = 1.0f / fmaxf(sqrtf(tot), 1e-12f);
        float v = x * inv;
        if (which == 0) g_e1n[l][r][d]  = v;
        else            g_e2nT[l][d][r] = v;
    } else if (bid < 4096) {
        // c1p = cert1 * 0.5*alpha
        int t = bid - 3072;
        int l = t / B, r = t % B;
        const float* c = (l == 0) ? c1_1 : c1_2;
        const float* a = (l == 0) ? a_1  : a_2;
        g_c1p[l][r][d] = c[r * D + d] * (0.5f * a[d]);
    } else if (bid < 5120) {
        // cert2 transpose
        int t = bid - 4096;
        int l = t / B, r = t % B;
        const float* c = (l == 0) ? c2_1 : c2_2;
        g_c2T[l][d][r] = c[r * D + d];
    } else if (bid == 5120) {
        g_bp[0][d] = 0.5f * b_1[d];
        g_bp[1][d] = 0.5f * b_2[d];
    } else {
        // top-3 per column + column normalization; bid 5121 -> link0, 5122 -> link1
        int m = bid - 5121;
        int e = d;
        const float* L = m ? link1 : link0;
        float v0 = -1e30f, v1 = -1e30f, v2 = -1e30f;
        int   i0 = 0, i1 = 0, i2 = 0;
        for (int r = 0; r < D; ++r) {
            float w = L[r * D + e];     // column e, row r
            if (w > v0)      { v2 = v1; i2 = i1; v1 = v0; i1 = i0; v0 = w; i0 = r; }
            else if (w > v1) { v2 = v1; i2 = i1; v1 = w;  i1 = r; }
            else if (w > v2) { v2 = w;  i2 = r; }
        }
        float inv = 1.0f / (v0 + v1 + v2 + 1e-8f);
        g_widx4[m][e] = make_int4(i0 * NHSTRIDE, i1 * NHSTRIDE, i2 * NHSTRIDE, 0);
        g_wval4[m][e] = make_float4(v0 * inv, v1 * inv, v2 * inv, 0.0f);
    }
}

// ---------------- fused similarity kernel ----------------
// block = (16 j-quads, 16 channel-groups); each thread: 8 channels x 4 j (float4).
// All shared gathers are LDS.128 conflict-free; all LDG are 128-bit coalesced.
__global__ __launch_bounds__(256) void avsl_main_kernel(float* __restrict__ out)
{
    __shared__ float  nh[D][NHSTRIDE];   // 32 KB: nh[d][j] for the current i
    __shared__ float  sE0[D];            // e1n layer0 (current i)
    __shared__ float  sE1[2][D];         // e1n layers 1,2
    __shared__ float  sC1[2][D];         // c1p layers 1,2
    __shared__ float  sBP[2][D];
    __shared__ int4   sIdx[2 * D];
    __shared__ float4 sVal[2 * D];
    __shared__ float4 sRed[8][16];

    const int tx  = threadIdx.x;        // 0..15  (j-quad)
    const int g   = threadIdx.y;        // 0..15  (channel group of 8)
    const int tid = g * 16 + tx;
    const int jj  = blockIdx.x * JT + tx * 4;
    const int i0  = blockIdx.y * TI;

    // stage W + bp once per block
    for (int t = tid; t < 2 * D; t += 256) {
        sIdx[t] = ((const int4*)g_widx4)[t];
        sVal[t] = ((const float4*)g_wval4)[t];
        ((float*)sBP)[t] = ((const float*)g_bp)[t];
    }

    for (int ii = 0; ii < TI; ++ii) {
        const int i = i0 + ii;
        __syncthreads();
        for (int t = tid; t < 5 * D; t += 256) {
            int seg = t >> 7, d = t & 127;
            float v;
            if (seg == 0)      v = g_e1n[0][i][d];
            else if (seg < 3)  v = g_e1n[seg][i][d];
            else               v = g_c1p[seg - 3][i][d];
            if (seg == 0)      sE0[d] = v;
            else if (seg < 3)  sE1[seg - 1][d] = v;
            else               sC1[seg - 3][d] = v;
        }
        __syncthreads();

        // ---- layer 0 ----
        #pragma unroll
        for (int k = 0; k < 8; ++k) {
            int e = g * 8 + k;
            float4 e2 = *(const float4*)&g_e2nT[0][e][jj];
            float  a  = sE0[e];
            float4 r;
            r.x = (a - e2.x) * (a - e2.x);
            r.y = (a - e2.y) * (a - e2.y);
            r.z = (a - e2.z) * (a - e2.z);
            r.w = (a - e2.w) * (a - e2.w);
            *(float4*)&nh[e][tx * 4] = r;
        }
        __syncthreads();

        // ---- layer 1 ----
        float4 tnh[8];
        const float* nb = &nh[0][0];
        #pragma unroll
        for (int k = 0; k < 8; ++k) {
            int e = g * 8 + k;
            int4   id = sIdx[e];
            float4 w  = sVal[e];
            float4 g0 = *(const float4*)(nb + id.x + tx * 4);
            float4 g1 = *(const float4*)(nb + id.y + tx * 4);
            float4 g2 = *(const float4*)(nb + id.z + tx * 4);
            float4 s;
            s.x = fmaf(w.z, g2.x, fmaf(w.y, g1.x, w.x * g0.x));
            s.y = fmaf(w.z, g2.y, fmaf(w.y, g1.y, w.x * g0.y));
            s.z = fmaf(w.z, g2.z, fmaf(w.y, g1.z, w.x * g0.z));
            s.w = fmaf(w.z, g2.w, fmaf(w.y, g1.w, w.x * g0.w));
            float4 e2 = *(const float4*)&g_e2nT[1][e][jj];
            float4 c2 = *(const float4*)&g_c2T[0][e][jj];
            float a  = sE1[0][e];
            float cp = sC1[0][e];
            float bp = sBP[0][e];
            float4 r;
            {
                float v = a - e2.x, n = v * v;
                float P = fmaf(0.5f, tanh_approx(fmaf(cp, c2.x, bp)), 0.5f);
                r.x = fmaf(P, n - s.x, s.x);
            }
            {
                float v = a - e2.y, n = v * v;
                float P = fmaf(0.5f, tanh_approx(fmaf(cp, c2.y, bp)), 0.5f);
                r.y = fmaf(P, n - s.y, s.y);
            }
            {
                float v = a - e2.z, n = v * v;
                float P = fmaf(0.5f, tanh_approx(fmaf(cp, c2.z, bp)), 0.5f);
                r.z = fmaf(P, n - s.z, s.z);
            }
            {
                float v = a - e2.w, n = v * v;
                float P = fmaf(0.5f, tanh_approx(fmaf(cp, c2.w, bp)), 0.5f);
                r.w = fmaf(P, n - s.w, s.w);
            }
            tnh[k] = r;
        }
        __syncthreads();
        #pragma unroll
        for (int k = 0; k < 8; ++k)
            *(float4*)&nh[g * 8 + k][tx * 4] = tnh[k];
        __syncthreads();

        // ---- layer 2 + channel sum ----
        float4 acc = make_float4(0.f, 0.f, 0.f, 0.f);
        #pragma unroll
        for (int k = 0; k < 8; ++k) {
            int e = g * 8 + k;
            int4   id = sIdx[D + e];
            float4 w  = sVal[D + e];
            float4 g0 = *(const float4*)(nb + id.x + tx * 4);
            float4 g1 = *(const float4*)(nb + id.y + tx * 4);
            float4 g2 = *(const float4*)(nb + id.z + tx * 4);
            float4 s;
            s.x = fmaf(w.z, g2.x, fmaf(w.y, g1.x, w.x * g0.x));
            s.y = fmaf(w.z, g2.y, fmaf(w.y, g1.y, w.x * g0.y));
            s.z = fmaf(w.z, g2.z, fmaf(w.y, g1.z, w.x * g0.z));
            s.w = fmaf(w.z, g2.w, fmaf(w.y, g1.w, w.x * g0.w));
            float4 e2 = *(const float4*)&g_e2nT[2][e][jj];
            float4 c2 = *(const float4*)&g_c2T[1][e][jj];
            float a  = sE1[1][e];
            float cp = sC1[1][e];
            float bp = sBP[1][e];
            {
                float v = a - e2.x, n = v * v;
                float P = fmaf(0.5f, tanh_approx(fmaf(cp, c2.x, bp)), 0.5f);
                acc.x += fmaf(P, n - s.x, s.x);
            }
            {
                float v = a - e2.y, n = v * v;
                float P = fmaf(0.5f, tanh_approx(fmaf(cp, c2.y, bp)), 0.5f);
                acc.y += fmaf(P, n - s.y, s.y);
            }
            {
                float v = a - e2.z, n = v * v;
                float P = fmaf(0.5f, tanh_approx(fmaf(cp, c2.z, bp)), 0.5f);
                acc.z += fmaf(P, n - s.z, s.z);
            }
            {
                float v = a - e2.w, n = v * v;
                float P = fmaf(0.5f, tanh_approx(fmaf(cp, c2.w, bp)), 0.5f);
                acc.w += fmaf(P, n - s.w, s.w);
            }
        }
        // intra-warp: combine the two channel-groups sharing a warp
        acc.x += __shfl_down_sync(0xffffffffu, acc.x, 16);
        acc.y += __shfl_down_sync(0xffffffffu, acc.y, 16);
        acc.z += __shfl_down_sync(0xffffffffu, acc.z, 16);
        acc.w += __shfl_down_sync(0xffffffffu, acc.w, 16);
        if ((g & 1) == 0) sRed[g >> 1][tx] = acc;
        __syncthreads();
        if (g == 0) {
            float4 t0 = sRed[0][tx], t1 = sRed[1][tx], t2 = sRed[2][tx], t3 = sRed[3][tx];
            float4 t4 = sRed[4][tx], t5 = sRed[5][tx], t6 = sRed[6][tx], t7 = sRed[7][tx];
            float4 tot;
            tot.x = ((t0.x + t1.x) + (t2.x + t3.x)) + ((t4.x + t5.x) + (t6.x + t7.x));
            tot.y = ((t0.y + t1.y) + (t2.y + t3.y)) + ((t4.y + t5.y) + (t6.y + t7.y));
            tot.z = ((t0.z + t1.z) + (t2.z + t3.z)) + ((t4.z + t5.z) + (t6.z + t7.z));
            tot.w = ((t0.w + t1.w) + (t2.w + t3.w)) + ((t4.w + t5.w) + (t6.w + t7.w));
            *(float4*)&out[i * B + jj] = tot;
        }
    }
}

// ---------------- launch ----------------
extern "C" void kernel_launch(void* const* d_in, const int* in_sizes, int n_in,
                              void* d_out, int out_size)
{
    (void)n_in; (void)out_size;

    const float *e1_0, *e1_1, *e1_2, *e2_0, *e2_1, *e2_2;
    const float *c1_1, *c1_2, *c2_1, *c2_2;
    const float *a_1, *a_2, *b_1, *b_2;
    const float *link0, *link1;

    // Detect input ordering at runtime via element counts (see round-1 note).
    if (in_sizes[4] == 128) {
        // dict insertion order (interleaved per layer)
        e1_0 = (const float*)d_in[0];   e2_0 = (const float*)d_in[1];
        e1_1 = (const float*)d_in[6];   e2_1 = (const float*)d_in[7];
        e1_2 = (const float*)d_in[12];  e2_2 = (const float*)d_in[13];
        c1_1 = (const float*)d_in[8];   c2_1 = (const float*)d_in[9];
        c1_2 = (const float*)d_in[14];  c2_2 = (const float*)d_in[15];
        a_1  = (const float*)d_in[10];  b_1  = (const float*)d_in[11];
        a_2  = (const float*)d_in[16];  b_2  = (const float*)d_in[17];
        link0 = (const float*)d_in[18]; link1 = (const float*)d_in[19];
    } else {
        // function-signature order (grouped)
        e1_0 = (const float*)d_in[0];   e1_1 = (const float*)d_in[1];
        e1_2 = (const float*)d_in[2];
        e2_0 = (const float*)d_in[3];   e2_1 = (const float*)d_in[4];
        e2_2 = (const float*)d_in[5];
        c1_1 = (const float*)d_in[7];   c1_2 = (const float*)d_in[8];
        c2_1 = (const float*)d_in[10];  c2_2 = (const float*)d_in[11];
        a_1  = (const float*)d_in[13];  a_2  = (const float*)d_in[14];
        b_1  = (const float*)d_in[16];  b_2  = (const float*)d_in[17];
        link0 = (const float*)d_in[18]; link1 = (const float*)d_in[19];
    }

    prep_kernel<<<5123, 128>>>(e1_0, e1_1, e1_2, e2_0, e2_1, e2_2,
                               c1_1, c1_2, c2_1, c2_2, a_1, a_2, b_1, b_2,
                               link0, link1);

    dim3 grid(B / JT, B / TI);   // (8, 256)
    dim3 blk(16, 16);
    avsl_main_kernel<<<grid, blk>>>((float*)d_out);
}

// round 5
// speedup vs baseline: 1.4435x; 1.0491x over previous
#include <cuda_runtime.h>

#define B 512
#define D 128
#define JT 32            // j per block
#define IB 2             // i per pass (register/LDG blocking)
#define NPASS 2          // passes per block -> block covers IB*NPASS i rows

// ---------------- device scratch (no allocation allowed) ----------------
__device__ float g_e1n[3][B][D];     // normalized emb1, row-major [l][i][d]
__device__ float g_e2nT[3][D][B];    // normalized emb2, TRANSPOSED [l][d][j]
__device__ float g_c1p[2][B][D];     // cert1_{1,2} * 0.5*alpha_{1,2}
__device__ float g_c2T[2][D][B];     // cert2_{1,2} transposed [l][d][j]
__device__ float g_bp[2][D];         // 0.5*beta_{1,2}
__device__ unsigned g_widxP[2][D];   // packed top-3 row indices (8 bits each)
__device__ float4 g_wval4[2][D];     // column-normalized top-3 weights, .w unused

__device__ __forceinline__ float tanh_approx(float x) {
    float y;
    asm("tanh.approx.f32 %0, %1;" : "=f"(y) : "f"(x));
    return y;
}

// ---------------- prep: normalize / transpose / scale / topk ----------------
__global__ void prep_kernel(
    const float* __restrict__ e1_0, const float* __restrict__ e1_1, const float* __restrict__ e1_2,
    const float* __restrict__ e2_0, const float* __restrict__ e2_1, const float* __restrict__ e2_2,
    const float* __restrict__ c1_1, const float* __restrict__ c1_2,
    const float* __restrict__ c2_1, const float* __restrict__ c2_2,
    const float* __restrict__ a_1,  const float* __restrict__ a_2,
    const float* __restrict__ b_1,  const float* __restrict__ b_2,
    const float* __restrict__ link0, const float* __restrict__ link1)
{
    __shared__ float sp[4];
    int bid = blockIdx.x;
    int d = threadIdx.x;   // 0..127

    if (bid < 3072) {
        // L2-normalize one embedding row
        int which = bid / 1536;            // 0 = emb1, 1 = emb2
        int t = bid % 1536;
        int l = t / B, r = t % B;
        const float* src = (which == 0)
            ? (l == 0 ? e1_0 : (l == 1 ? e1_1 : e1_2))
            : (l == 0 ? e2_0 : (l == 1 ? e2_1 : e2_2));
        float x = src[r * D + d];
        float ss = x * x;
        #pragma unroll
        for (int o = 16; o; o >>= 1) ss += __shfl_xor_sync(0xffffffffu, ss, o);
        if ((d & 31) == 0) sp[d >> 5] = ss;
        __syncthreads();
        float tot = sp[0] + sp[1] + sp[2] + sp[3];
        float inv = 1.0f / fmaxf(sqrtf(tot), 1e-12f);
        float v = x * inv;
        if (which == 0) g_e1n[l][r][d]  = v;
        else            g_e2nT[l][d][r] = v;
    } else if (bid < 4096) {
        // c1p = cert1 * 0.5*alpha
        int t = bid - 3072;
        int l = t / B, r = t % B;
        const float* c = (l == 0) ? c1_1 : c1_2;
        const float* a = (l == 0) ? a_1  : a_2;
        g_c1p[l][r][d] = c[r * D + d] * (0.5f * a[d]);
    } else if (bid < 5120) {
        // cert2 transpose
        int t = bid - 4096;
        int l = t / B, r = t % B;
        const float* c = (l == 0) ? c2_1 : c2_2;
        g_c2T[l][d][r] = c[r * D + d];
    } else if (bid == 5120) {
        g_bp[0][d] = 0.5f * b_1[d];
        g_bp[1][d] = 0.5f * b_2[d];
    } else {
        // top-3 per column + column normalization; bid 5121 -> link0, 5122 -> link1
        int m = bid - 5121;
        int e = d;
        const float* L = m ? link1 : link0;
        float v0 = -1e30f, v1 = -1e30f, v2 = -1e30f;
        int   i0 = 0, i1 = 0, i2 = 0;
        for (int r = 0; r < D; ++r) {
            float w = L[r * D + e];     // column e, row r
            if (w > v0)      { v2 = v1; i2 = i1; v1 = v0; i1 = i0; v0 = w; i0 = r; }
            else if (w > v1) { v2 = v1; i2 = i1; v1 = w;  i1 = r; }
            else if (w > v2) { v2 = w;  i2 = r; }
        }
        float inv = 1.0f / (v0 + v1 + v2 + 1e-8f);
        g_widxP[m][e] = (unsigned)i0 | ((unsigned)i1 << 8) | ((unsigned)i2 << 16);
        g_wval4[m][e] = make_float4(v0 * inv, v1 * inv, v2 * inv, 0.0f);
    }
}

// ---------------- fused similarity kernel ----------------
// block = 512 threads = (8 j-quads, 64 channel-pairs); each thread: 2 channels x
// 2 i x 4 j (float4). Every e2/c2 LDG.128 serves 8 pairs; all shared gathers are
// conflict-free LDS.128 (rows are exactly 128B).
__global__ __launch_bounds__(512, 2) void avsl_main_kernel(float* __restrict__ out)
{
    __shared__ float    nh[IB][D][JT];      // 32 KB
    __shared__ unsigned sIdxP[2][D];        // 1 KB
    __shared__ float4   sVal[2][D];         // 4 KB
    __shared__ float    sE0[IB][D];         // 1 KB
    __shared__ float    sE1[2][IB][D];      // 2 KB
    __shared__ float    sC1[2][IB][D];      // 2 KB
    __shared__ float    sBP[2][D];          // 1 KB
    __shared__ float4   sRed[16][8][IB];    // 4 KB   (total 48128 B)

    const int q   = threadIdx.x;           // 0..7   (j-quad)
    const int g   = threadIdx.y;           // 0..63  (channel pair)
    const int tid = g * 8 + q;
    const int jj  = blockIdx.x * JT + q * 4;

    // stage W + bp once per block (each smem word written by exactly one thread)
    if (tid < 2 * D) {
        ((unsigned*)sIdxP)[tid] = ((const unsigned*)g_widxP)[tid];
        ((float4*)sVal)[tid]    = ((const float4*)g_wval4)[tid];
        ((float*)sBP)[tid]      = ((const float*)g_bp)[tid];
    }

    for (int ip = 0; ip < NPASS; ++ip) {
        const int i_base = blockIdx.y * (IB * NPASS) + ip * IB;
        __syncthreads();
        // stage per-pass i-side data: 5 segments x IB x D = 1280 floats
        for (int t = tid; t < 5 * IB * D; t += 512) {
            int seg = t / (IB * D);
            int rem = t - seg * (IB * D);
            int ii = rem >> 7, d = rem & 127;
            int i = i_base + ii;
            if (seg == 0)      sE0[ii][d]          = g_e1n[0][i][d];
            else if (seg < 3)  sE1[seg - 1][ii][d] = g_e1n[seg][i][d];
            else               sC1[seg - 3][ii][d] = g_c1p[seg - 3][i][d];
        }
        __syncthreads();

        // ---- layer 0 ----
        #pragma unroll
        for (int k = 0; k < 2; ++k) {
            int e = g * 2 + k;
            float4 e2 = *(const float4*)&g_e2nT[0][e][jj];
            #pragma unroll
            for (int ii = 0; ii < IB; ++ii) {
                float a = sE0[ii][e];
                float4 r;
                r.x = (a - e2.x) * (a - e2.x);
                r.y = (a - e2.y) * (a - e2.y);
                r.z = (a - e2.z) * (a - e2.z);
                r.w = (a - e2.w) * (a - e2.w);
                *(float4*)&nh[ii][e][q * 4] = r;
            }
        }
        __syncthreads();

        // ---- layer 1 ----
        float4 tnh[2][IB];
        #pragma unroll
        for (int k = 0; k < 2; ++k) {
            int e = g * 2 + k;
            unsigned p = sIdxP[0][e];
            int o0 = (int)(p & 255u) * JT;
            int o1 = (int)((p >> 8) & 255u) * JT;
            int o2 = (int)((p >> 16) & 255u) * JT;
            float4 w  = sVal[0][e];
            float4 e2 = *(const float4*)&g_e2nT[1][e][jj];
            float4 c2 = *(const float4*)&g_c2T[0][e][jj];
            float bp = sBP[0][e];
            #pragma unroll
            for (int ii = 0; ii < IB; ++ii) {
                const float* nb = &nh[ii][0][0];
                float4 g0 = *(const float4*)(nb + o0 + q * 4);
                float4 g1 = *(const float4*)(nb + o1 + q * 4);
                float4 g2 = *(const float4*)(nb + o2 + q * 4);
                float a  = sE1[0][ii][e];
                float cp = sC1[0][ii][e];
                float4 r;
                {
                    float s = fmaf(w.z, g2.x, fmaf(w.y, g1.x, w.x * g0.x));
                    float v = a - e2.x, n = v * v;
                    float P = fmaf(0.5f, tanh_approx(fmaf(cp, c2.x, bp)), 0.5f);
                    r.x = fmaf(P, n - s, s);
                }
                {
                    float s = fmaf(w.z, g2.y, fmaf(w.y, g1.y, w.x * g0.y));
                    float v = a - e2.y, n = v * v;
                    float P = fmaf(0.5f, tanh_approx(fmaf(cp, c2.y, bp)), 0.5f);
                    r.y = fmaf(P, n - s, s);
                }
                {
                    float s = fmaf(w.z, g2.z, fmaf(w.y, g1.z, w.x * g0.z));
                    float v = a - e2.z, n = v * v;
                    float P = fmaf(0.5f, tanh_approx(fmaf(cp, c2.z, bp)), 0.5f);
                    r.z = fmaf(P, n - s, s);
                }
                {
                    float s = fmaf(w.z, g2.w, fmaf(w.y, g1.w, w.x * g0.w));
                    float v = a - e2.w, n = v * v;
                    float P = fmaf(0.5f, tanh_approx(fmaf(cp, c2.w, bp)), 0.5f);
                    r.w = fmaf(P, n - s, s);
                }
                tnh[k][ii] = r;
            }
        }
        __syncthreads();
        #pragma unroll
        for (int k = 0; k < 2; ++k)
            #pragma unroll
            for (int ii = 0; ii < IB; ++ii)
                *(float4*)&nh[ii][g * 2 + k][q * 4] = tnh[k][ii];
        __syncthreads();

        // ---- layer 2 + channel sum ----
        float4 acc[IB];
        #pragma unroll
        for (int ii = 0; ii < IB; ++ii) acc[ii] = make_float4(0.f, 0.f, 0.f, 0.f);
        #pragma unroll
        for (int k = 0; k < 2; ++k) {
            int e = g * 2 + k;
            unsigned p = sIdxP[1][e];
            int o0 = (int)(p & 255u) * JT;
            int o1 = (int)((p >> 8) & 255u) * JT;
            int o2 = (int)((p >> 16) & 255u) * JT;
            float4 w  = sVal[1][e];
            float4 e2 = *(const float4*)&g_e2nT[2][e][jj];
            float4 c2 = *(const float4*)&g_c2T[1][e][jj];
            float bp = sBP[1][e];
            #pragma unroll
            for (int ii = 0; ii < IB; ++ii) {
                const float* nb = &nh[ii][0][0];
                float4 g0 = *(const float4*)(nb + o0 + q * 4);
                float4 g1 = *(const float4*)(nb + o1 + q * 4);
                float4 g2 = *(const float4*)(nb + o2 + q * 4);
                float a  = sE1[1][ii][e];
                float cp = sC1[1][ii][e];
                {
                    float s = fmaf(w.z, g2.x, fmaf(w.y, g1.x, w.x * g0.x));
                    float v = a - e2.x, n = v * v;
                    float P = fmaf(0.5f, tanh_approx(fmaf(cp, c2.x, bp)), 0.5f);
                    acc[ii].x += fmaf(P, n - s, s);
                }
                {
                    float s = fmaf(w.z, g2.y, fmaf(w.y, g1.y, w.x * g0.y));
                    float v = a - e2.y, n = v * v;
                    float P = fmaf(0.5f, tanh_approx(fmaf(cp, c2.y, bp)), 0.5f);
                    acc[ii].y += fmaf(P, n - s, s);
                }
                {
                    float s = fmaf(w.z, g2.z, fmaf(w.y, g1.z, w.x * g0.z));
                    float v = a - e2.z, n = v * v;
                    float P = fmaf(0.5f, tanh_approx(fmaf(cp, c2.z, bp)), 0.5f);
                    acc[ii].z += fmaf(P, n - s, s);
                }
                {
                    float s = fmaf(w.z, g2.w, fmaf(w.y, g1.w, w.x * g0.w));
                    float v = a - e2.w, n = v * v;
                    float P = fmaf(0.5f, tanh_approx(fmaf(cp, c2.w, bp)), 0.5f);
                    acc[ii].w += fmaf(P, n - s, s);
                }
            }
        }
        // combine the 4 channel-pair subgroups within each warp (lanes g%4)
        #pragma unroll
        for (int ii = 0; ii < IB; ++ii) {
            acc[ii].x += __shfl_down_sync(0xffffffffu, acc[ii].x, 16);
            acc[ii].y += __shfl_down_sync(0xffffffffu, acc[ii].y, 16);
            acc[ii].z += __shfl_down_sync(0xffffffffu, acc[ii].z, 16);
            acc[ii].w += __shfl_down_sync(0xffffffffu, acc[ii].w, 16);
            acc[ii].x += __shfl_down_sync(0xffffffffu, acc[ii].x, 8);
            acc[ii].y += __shfl_down_sync(0xffffffffu, acc[ii].y, 8);
            acc[ii].z += __shfl_down_sync(0xffffffffu, acc[ii].z, 8);
            acc[ii].w += __shfl_down_sync(0xffffffffu, acc[ii].w, 8);
        }
        if ((g & 3) == 0) {
            int w = g >> 2;   // warp id 0..15
            #pragma unroll
            for (int ii = 0; ii < IB; ++ii) sRed[w][q][ii] = acc[ii];
        }
        __syncthreads();
        if (tid < 8 * IB) {
            int quad = tid & 7, ii = tid >> 3;
            float4 tot = make_float4(0.f, 0.f, 0.f, 0.f);
            #pragma unroll
            for (int w = 0; w < 16; ++w) {
                float4 t = sRed[w][quad][ii];
                tot.x += t.x; tot.y += t.y; tot.z += t.z; tot.w += t.w;
            }
            *(float4*)&out[(i_base + ii) * B + blockIdx.x * JT + quad * 4] = tot;
        }
    }
}

// ---------------- launch ----------------
extern "C" void kernel_launch(void* const* d_in, const int* in_sizes, int n_in,
                              void* d_out, int out_size)
{
    (void)n_in; (void)out_size;

    const float *e1_0, *e1_1, *e1_2, *e2_0, *e2_1, *e2_2;
    const float *c1_1, *c1_2, *c2_1, *c2_2;
    const float *a_1, *a_2, *b_1, *b_2;
    const float *link0, *link1;

    // Detect input ordering at runtime via element counts (see round-1 note).
    if (in_sizes[4] == 128) {
        // dict insertion order (interleaved per layer)
        e1_0 = (const float*)d_in[0];   e2_0 = (const float*)d_in[1];
        e1_1 = (const float*)d_in[6];   e2_1 = (const float*)d_in[7];
        e1_2 = (const float*)d_in[12];  e2_2 = (const float*)d_in[13];
        c1_1 = (const float*)d_in[8];   c2_1 = (const float*)d_in[9];
        c1_2 = (const float*)d_in[14];  c2_2 = (const float*)d_in[15];
        a_1  = (const float*)d_in[10];  b_1  = (const float*)d_in[11];
        a_2  = (const float*)d_in[16];  b_2  = (const float*)d_in[17];
        link0 = (const float*)d_in[18]; link1 = (const float*)d_in[19];
    } else {
        // function-signature order (grouped)
        e1_0 = (const float*)d_in[0];   e1_1 = (const float*)d_in[1];
        e1_2 = (const float*)d_in[2];
        e2_0 = (const float*)d_in[3];   e2_1 = (const float*)d_in[4];
        e2_2 = (const float*)d_in[5];
        c1_1 = (const float*)d_in[7];   c1_2 = (const float*)d_in[8];
        c2_1 = (const float*)d_in[10];  c2_2 = (const float*)d_in[11];
        a_1  = (const float*)d_in[13];  a_2  = (const float*)d_in[14];
        b_1  = (const float*)d_in[16];  b_2  = (const float*)d_in[17];
        link0 = (const float*)d_in[18]; link1 = (const float*)d_in[19];
    }

    prep_kernel<<<5123, 128>>>(e1_0, e1_1, e1_2, e2_0, e2_1, e2_2,
                               c1_1, c1_2, c2_1, c2_2, a_1, a_2, b_1, b_2,
                               link0, link1);

    dim3 grid(B / JT, B / (IB * NPASS));   // (16, 128)
    dim3 blk(8, 64);
    avsl_main_kernel<<<grid, blk>>>((float*)d_out);
}